// round 13
// baseline (speedup 1.0000x reference)
#include <cuda_runtime.h>
#include <cstdint>
#include <cstddef>

// Binarized 6-layer MLP, exact integer formulation.
// Round 12: layer-1 GEMM moved to int8 tensor cores (mma.sync m16n8k32 s8s8s32,
// exact: |dot|<=4096). x and W1 packed as +/-1 int8; tail unchanged (round-11).

#define MB 16384
#define TAIL_CTAS 432
#define TAIL_THREADS 256

// ---------------- static device scratch ----------------
__device__ __align__(16) signed char g_xi8[(size_t)MB * 4096];   // 64 MB
__device__ __align__(16) signed char g_wi8[512 * 4096];          // 2 MB (rows 500-511 zero)
__device__ __align__(16) unsigned g_act0[MB * 128];              // 8 MB (tail act buffer)
__device__ __align__(16) unsigned g_act1[MB * 16];               // 1 MB
__device__ __align__(16) unsigned g_wb[6][64000];                // bit-packed W (l=1..5 used)
__device__ int                    g_sb[6][512];
__device__ __align__(16) short    g_aout[(size_t)MB * 512];
__device__ int                    g_sumA[2][512];
__device__ unsigned long long     g_sum2A[2][512];

struct __align__(128) LeafCtr { unsigned v; unsigned pad[31]; };
__device__ LeafCtr                g_leaf[16];
__device__ unsigned               g_root;
__device__ volatile unsigned      g_gen;

// ---------------- one-shot prep ----------------
struct BiasPtrs { const float* b[6]; };

__global__ void prep_kernel(BiasPtrs bp) {
    int j = threadIdx.x;   // 512 threads
    static const int LNc[6] = {500, 400, 350, 300, 300, 35};
#pragma unroll
    for (int l = 0; l < 6; l++)
        if (j < LNc[l]) g_sb[l][j] = (bp.b[l][j] < 0.0f) ? -1 : 1;
    g_sumA[0][j] = 0;  g_sumA[1][j] = 0;
    g_sum2A[0][j] = 0ull; g_sum2A[1][j] = 0ull;
    if (j < 16) g_leaf[j].v = 0u;
    if (j == 0) { g_root = 0u; g_gen = 0u; }
}

// zero W1 pad rows 500..511 (12 * 4096 B = 3072 uint4)
__global__ void wpad_kernel() {
    int i = blockIdx.x * blockDim.x + threadIdx.x;
    if (i < 3072)
        ((uint4*)(g_wi8 + 500 * 4096))[i] = make_uint4(0, 0, 0, 0);
}

// ---------------- fused sign-pack ----------------
// fmt 1: +/-1 int8 (x, W1; C==4096, unit=128 cols). fmt 0: bit-pack (W2..W6).
struct PackRegions {
    const float* src[7];
    void*        dst[7];
    int R[7], C[7], KW[7], G[7], fmt[7];
    long long units[7];
    long long total;
};

__global__ void pack_all_kernel(PackRegions pr) {
    const int lane = threadIdx.x & 31;
    const int wid  = threadIdx.x >> 5;
    const long long stride = (long long)gridDim.x * (blockDim.x / 32);
    for (long long gw = (long long)blockIdx.x * (blockDim.x / 32) + wid;
         gw < pr.total; gw += stride) {
        long long u = gw;
        int r = 0;
        while (u >= pr.units[r]) { u -= pr.units[r]; r++; }
        const int G = pr.G[r], C = pr.C[r], KW = pr.KW[r];
        const int row = (int)(u / G);
        const int g   = (int)(u - (long long)row * G);
        if (pr.fmt[r]) {
            // int8 path: C = 4096, 128 cols per unit
            const float4 v = *(const float4*)((const float*)pr.src[r]
                                              + (size_t)row * 4096 + g * 128 + lane * 4);
            char4 c;
            c.x = (v.x < 0.0f) ? -1 : 1;
            c.y = (v.y < 0.0f) ? -1 : 1;
            c.z = (v.z < 0.0f) ? -1 : 1;
            c.w = (v.w < 0.0f) ? -1 : 1;
            *(char4*)((signed char*)pr.dst[r] + (size_t)row * 4096 + g * 128 + lane * 4) = c;
        } else {
            const int w0 = g * 4;
            const float* src = (const float*)pr.src[r] + (size_t)row * C;
            float v[4];
#pragma unroll
            for (int k = 0; k < 4; k++) {
                int col = (w0 + k) * 32 + lane;
                v[k] = (w0 + k < KW && col < C) ? src[col] : 0.0f;
            }
#pragma unroll
            for (int k = 0; k < 4; k++) {
                unsigned m = __ballot_sync(0xffffffffu, v[k] < 0.0f);
                if (lane == 0 && w0 + k < KW)
                    ((unsigned*)pr.dst[r])[(size_t)row * KW + w0 + k] = m;
            }
        }
    }
}

// ---------------- layer-1 GEMM: int8 tensor cores ----------------
// M=16384, N=512(500 real), K=4096. CTA 128x128, 8 warps (2m x 4n), warp 64x32.
// K chunks of 64 int8, double-buffered smem, rows padded to 80 B (conflict-free
// 32-lane fragment loads). Fused per-column stats.
#define SROW 80

__device__ __forceinline__ void mma_s8(int* d, const unsigned* a, const unsigned* b) {
    asm volatile(
        "mma.sync.aligned.m16n8k32.row.col.s32.s8.s8.s32 "
        "{%0,%1,%2,%3}, {%4,%5,%6,%7}, {%8,%9}, {%0,%1,%2,%3};\n"
        : "+r"(d[0]), "+r"(d[1]), "+r"(d[2]), "+r"(d[3])
        : "r"(a[0]), "r"(a[1]), "r"(a[2]), "r"(a[3]), "r"(b[0]), "r"(b[1]));
}

__global__ void __launch_bounds__(256, 2)
gemm1_kernel(const signed char* __restrict__ xi8, const signed char* __restrict__ wi8,
             const int* __restrict__ sb, short* __restrict__ out) {
    __shared__ __align__(16) char As[2][128 * SROW];
    __shared__ __align__(16) char Bs[2][128 * SROW];
    __shared__ int s_sum[128];
    __shared__ unsigned s_sq[128];

    const int tid = threadIdx.x;
    const int lane = tid & 31;
    const int wid = tid >> 5;
    const int warp_m = wid >> 2;          // 0..1 (64 rows each)
    const int warp_n = wid & 3;           // 0..3 (32 cols each)
    const int gq = lane >> 2;             // groupID 0..7
    const int tg = lane & 3;              // threadID_in_group
    const int row0 = blockIdx.y * 128;
    const int col0 = blockIdx.x * 128;

    if (tid < 128) { s_sum[tid] = 0; s_sq[tid] = 0u; }

    int acc[4][4][4];
#pragma unroll
    for (int mf = 0; mf < 4; mf++)
#pragma unroll
        for (int nf = 0; nf < 4; nf++)
#pragma unroll
            for (int e = 0; e < 4; e++) acc[mf][nf][e] = 0;

    const int fr = tid >> 2;              // 0..63 (fill row)
    const int fc = tid & 3;               // 16B column within 64B row chunk

    uint4 pa0, pa1, pb0, pb1;
    {   // prologue chunk 0
        pa0 = *(const uint4*)(xi8 + (size_t)(row0 + fr) * 4096 + fc * 16);
        pa1 = *(const uint4*)(xi8 + (size_t)(row0 + fr + 64) * 4096 + fc * 16);
        pb0 = *(const uint4*)(wi8 + (size_t)(col0 + fr) * 4096 + fc * 16);
        pb1 = *(const uint4*)(wi8 + (size_t)(col0 + fr + 64) * 4096 + fc * 16);
        *(uint4*)(As[0] + fr * SROW + fc * 16) = pa0;
        *(uint4*)(As[0] + (fr + 64) * SROW + fc * 16) = pa1;
        *(uint4*)(Bs[0] + fr * SROW + fc * 16) = pb0;
        *(uint4*)(Bs[0] + (fr + 64) * SROW + fc * 16) = pb1;
    }
    __syncthreads();

#pragma unroll 1
    for (int ch = 0; ch < 64; ch++) {
        const int buf = ch & 1;
        if (ch < 63) {
            const size_t kc = (size_t)(ch + 1) * 64;
            pa0 = *(const uint4*)(xi8 + (size_t)(row0 + fr) * 4096 + kc + fc * 16);
            pa1 = *(const uint4*)(xi8 + (size_t)(row0 + fr + 64) * 4096 + kc + fc * 16);
            pb0 = *(const uint4*)(wi8 + (size_t)(col0 + fr) * 4096 + kc + fc * 16);
            pb1 = *(const uint4*)(wi8 + (size_t)(col0 + fr + 64) * 4096 + kc + fc * 16);
        }
        const char* ab = As[buf];
        const char* bb = Bs[buf];
#pragma unroll
        for (int ks = 0; ks < 2; ks++) {
            unsigned a[4][4], b[4][2];
#pragma unroll
            for (int mf = 0; mf < 4; mf++) {
                const char* p = ab + (warp_m * 64 + mf * 16 + gq) * SROW + ks * 32 + tg * 4;
                a[mf][0] = *(const unsigned*)(p);
                a[mf][1] = *(const unsigned*)(p + 8 * SROW);
                a[mf][2] = *(const unsigned*)(p + 16);
                a[mf][3] = *(const unsigned*)(p + 8 * SROW + 16);
            }
#pragma unroll
            for (int nf = 0; nf < 4; nf++) {
                const char* p = bb + (warp_n * 32 + nf * 8 + gq) * SROW + ks * 32 + tg * 4;
                b[nf][0] = *(const unsigned*)(p);
                b[nf][1] = *(const unsigned*)(p + 16);
            }
#pragma unroll
            for (int mf = 0; mf < 4; mf++)
#pragma unroll
                for (int nf = 0; nf < 4; nf++)
                    mma_s8(acc[mf][nf], a[mf], b[nf]);
        }
        if (ch < 63) {
            const int nb = buf ^ 1;
            *(uint4*)(As[nb] + fr * SROW + fc * 16) = pa0;
            *(uint4*)(As[nb] + (fr + 64) * SROW + fc * 16) = pa1;
            *(uint4*)(Bs[nb] + fr * SROW + fc * 16) = pb0;
            *(uint4*)(Bs[nb] + (fr + 64) * SROW + fc * 16) = pb1;
        }
        __syncthreads();
    }

    // epilogue: v = dot + sb[col]; store short pairs; fused stats.
    int sbr[4][2];
#pragma unroll
    for (int nf = 0; nf < 4; nf++) {
        int gcol = col0 + warp_n * 32 + nf * 8 + tg * 2;
        sbr[nf][0] = sb[gcol];
        sbr[nf][1] = sb[gcol + 1];
    }
    int ssum[8];
    unsigned ssq[8];
#pragma unroll
    for (int i = 0; i < 8; i++) { ssum[i] = 0; ssq[i] = 0u; }

#pragma unroll
    for (int mf = 0; mf < 4; mf++) {
        int r = row0 + warp_m * 64 + mf * 16 + gq;
#pragma unroll
        for (int nf = 0; nf < 4; nf++) {
            int jloc = warp_n * 32 + nf * 8 + tg * 2;
            int gcol = col0 + jloc;
            int v00 = acc[mf][nf][0] + sbr[nf][0];
            int v01 = acc[mf][nf][1] + sbr[nf][1];
            int v10 = acc[mf][nf][2] + sbr[nf][0];
            int v11 = acc[mf][nf][3] + sbr[nf][1];
            if (gcol + 1 < 500) {   // 500 even, gcol even: both or neither
                *(int*)(out + (size_t)r * 500 + gcol) =
                    ((unsigned)v00 & 0xFFFFu) | ((unsigned)v01 << 16);
                *(int*)(out + (size_t)(r + 8) * 500 + gcol) =
                    ((unsigned)v10 & 0xFFFFu) | ((unsigned)v11 << 16);
            }
            ssum[nf * 2 + 0] += v00 + v10;
            ssum[nf * 2 + 1] += v01 + v11;
            ssq[nf * 2 + 0] += (unsigned)(v00 * v00) + (unsigned)(v10 * v10);
            ssq[nf * 2 + 1] += (unsigned)(v01 * v01) + (unsigned)(v11 * v11);
        }
    }
    // reduce over the 8 lanes sharing tg (masks 4,8,16)
#pragma unroll
    for (int i = 0; i < 8; i++) {
#pragma unroll
        for (int m = 4; m <= 16; m <<= 1) {
            ssum[i] += __shfl_xor_sync(0xffffffffu, ssum[i], m);
            ssq[i]  += __shfl_xor_sync(0xffffffffu, ssq[i],  m);
        }
    }
    if (lane < 4) {   // gq == 0, tg == lane
#pragma unroll
        for (int nf = 0; nf < 4; nf++)
#pragma unroll
            for (int e = 0; e < 2; e++) {
                int cc = warp_n * 32 + nf * 8 + lane * 2 + e;
                atomicAdd(&s_sum[cc], ssum[nf * 2 + e]);
                atomicAdd(&s_sq[cc],  ssq[nf * 2 + e]);
            }
    }
    __syncthreads();
    if (tid < 128 && col0 + tid < 500) {
        atomicAdd(&g_sumA[0][col0 + tid], s_sum[tid]);
        atomicAdd(&g_sum2A[0][col0 + tid], (unsigned long long)s_sq[tid]);
    }
}

// ================= persistent tail kernel (round-11, unchanged) =================
struct TailPtrs { const float* gam[5]; const float* bet[5]; };

__device__ __forceinline__ void gsync() {
    __syncthreads();
    if (threadIdx.x == 0) {
        __threadfence();
        unsigned gen = g_gen;
        int leaf = blockIdx.x & 15;
        unsigned t = atomicAdd(&g_leaf[leaf].v, 1u);
        if (t == (TAIL_CTAS / 16 - 1)) {
            g_leaf[leaf].v = 0u;
            unsigned r = atomicAdd(&g_root, 1u);
            if (r == 15u) {
                g_root = 0u;
                __threadfence();
                g_gen = gen + 1u;
            } else {
                while (g_gen == gen) __nanosleep(64);
            }
        } else {
            while (g_gen == gen) __nanosleep(64);
        }
        __threadfence();
    }
    __syncthreads();
}

__device__ void thresh_smem(int l, const float* __restrict__ gam,
                            const float* __restrict__ bet, int N,
                            int* s_thr, unsigned char* s_mode) {
    int buf = l & 1, nxt = buf ^ 1;
    for (int j = threadIdx.x; j < 512; j += TAIL_THREADS) {
        g_sumA[nxt][j] = 0; g_sum2A[nxt][j] = 0ull;
    }
    for (int j = threadIdx.x; j < N; j += TAIL_THREADS) {
        double mean = (double)g_sumA[buf][j] / 16384.0;
        double var  = (double)(long long)g_sum2A[buf][j] / 16384.0 - mean * mean;
        double invstd = 1.0 / sqrt(var + 1e-5);
        double scale = invstd * (double)gam[j];
        double shift = (double)bet[j];
        int thr, mode;
        if (scale > 0.0) {
            double t = fmin(fmax(mean - shift / scale, -1.0e9), 1.0e9);
            thr = (int)ceil(t);  mode = 0;
        } else if (scale < 0.0) {
            double t = fmin(fmax(mean - shift / scale, -1.0e9), 1.0e9);
            thr = (int)floor(t); mode = 1;
        } else {
            mode = 0;
            thr = (shift < 0.0) ? 2147483647 : (-2147483647 - 1);
        }
        s_thr[j] = thr;
        s_mode[j] = (unsigned char)mode;
    }
    __syncthreads();
}

template <int C, int NP, int KW>
__device__ void pack_act_layer(const short* __restrict__ a, unsigned* __restrict__ dst,
                               const int* s_thr, const unsigned char* s_mode) {
    const int wid = threadIdx.x >> 5, lane = threadIdx.x & 31;
    const int gw = blockIdx.x * (TAIL_THREADS / 32) + wid;
    const int total = TAIL_CTAS * (TAIL_THREADS / 32);
    for (int row = gw; row < MB; row += total) {
        const short* ar = a + (size_t)row * NP;
        unsigned* dr = dst + (size_t)row * KW;
#pragma unroll
        for (int w0 = 0; w0 < KW; w0 += 8) {
            const int nb = (KW - w0 < 8) ? (KW - w0) : 8;
            int v[8];
#pragma unroll
            for (int k = 0; k < 8; k++) {
                if (k < nb) {
                    int col = (w0 + k) * 32 + lane;
                    v[k] = (col < C) ? (int)ar[col] : 0;
                }
            }
            unsigned m[8];
#pragma unroll
            for (int k = 0; k < 8; k++) {
                if (k < nb) {
                    int col = (w0 + k) * 32 + lane;
                    bool neg = false;
                    if (col < C) {
                        int thr = s_thr[col];
                        neg = s_mode[col] ? (v[k] > thr) : (v[k] < thr);
                    }
                    m[k] = __ballot_sync(0xffffffffu, neg);
                }
            }
            if (lane == 0) {
#pragma unroll
                for (int k = 0; k < 8; k++)
                    if (k < nb) dr[w0 + k] = m[k];
            }
        }
    }
}

template <int N, int NP, int K, int KW, bool FINAL, int SB>
__device__ void gemm_layer(const unsigned* __restrict__ abits, const unsigned* __restrict__ bbits,
                           const int* __restrict__ sb, short* __restrict__ aout,
                           float* __restrict__ fout, unsigned one, unsigned hi,
                           unsigned* As, unsigned* Bs, int* s_sum, unsigned* s_sq) {
    const int tx = threadIdx.x & 15;
    const int ty = threadIdx.x >> 4;
    const int lane = threadIdx.x & 31;
    const int ct = (N + 63) / 64;
    const int ntiles = (MB / 64) * ct;

    if (!FINAL) {
        for (int idx = threadIdx.x; idx < 512; idx += 256) { s_sum[idx] = 0; s_sq[idx] = 0u; }
    }
    __syncthreads();

    for (int t = blockIdx.x; t < ntiles; t += TAIL_CTAS) {
        const int row0 = (t / ct) * 64;
        const int col0 = (t % ct) * 64;

        unsigned acc[4][2];
#pragma unroll
        for (int i = 0; i < 4; i++) { acc[i][0] = 0u; acc[i][1] = 0u; }

        for (int idx = threadIdx.x; idx < 64 * 16; idx += 256) {
            int r = idx >> 4, w = idx & 15;
            As[r * 17 + w] = (w < KW) ? abits[(size_t)(row0 + r) * KW + w] : 0u;
        }
        for (int idx = threadIdx.x; idx < 64 * 16; idx += 256) {
            int c = idx & 63, w = idx >> 6;
            int col = col0 + c;
            Bs[w * 64 + c] = (col < N && w < KW) ? bbits[(size_t)col * KW + w] : 0u;
        }
        __syncthreads();

#pragma unroll
        for (int w = 0; w < KW; w++) {
            unsigned a0 = As[(ty * 4 + 0) * 17 + w];
            unsigned a1 = As[(ty * 4 + 1) * 17 + w];
            unsigned a2 = As[(ty * 4 + 2) * 17 + w];
            unsigned a3 = As[(ty * 4 + 3) * 17 + w];
            uint4 bv = *(const uint4*)&Bs[w * 64 + tx * 4];
            acc[0][0] += __popc(a0 ^ bv.x) * one + __popc(a0 ^ bv.y) * hi;
            acc[0][1] += __popc(a0 ^ bv.z) * one + __popc(a0 ^ bv.w) * hi;
            acc[1][0] += __popc(a1 ^ bv.x) * one + __popc(a1 ^ bv.y) * hi;
            acc[1][1] += __popc(a1 ^ bv.z) * one + __popc(a1 ^ bv.w) * hi;
            acc[2][0] += __popc(a2 ^ bv.x) * one + __popc(a2 ^ bv.y) * hi;
            acc[2][1] += __popc(a2 ^ bv.z) * one + __popc(a2 ^ bv.w) * hi;
            acc[3][0] += __popc(a3 ^ bv.x) * one + __popc(a3 ^ bv.y) * hi;
            acc[3][1] += __popc(a3 ^ bv.z) * one + __popc(a3 ^ bv.w) * hi;
        }

        int sbr[4];
        const int c0b = col0 + tx * 4;
#pragma unroll
        for (int j = 0; j < 4; j++) sbr[j] = sb[c0b + j];

        int s_loc[4];
        unsigned q_loc[4];
#pragma unroll
        for (int j = 0; j < 4; j++) { s_loc[j] = 0; q_loc[j] = 0; }

#pragma unroll
        for (int i = 0; i < 4; i++) {
            int row = row0 + ty * 4 + i;
            int v[4];
#pragma unroll
            for (int jj = 0; jj < 2; jj++) {
                v[jj * 2 + 0] = K - 2 * (int)(acc[i][jj] & 0xFFFFu) + sbr[jj * 2 + 0];
                v[jj * 2 + 1] = K - 2 * (int)(acc[i][jj] >> 16)     + sbr[jj * 2 + 1];
            }
            if (FINAL) {
#pragma unroll
                for (int j = 0; j < 4; j++)
                    if (c0b + j < N) fout[(size_t)row * N + c0b + j] = (float)v[j];
            } else {
                if (c0b + 3 < NP) {
                    *(short4*)(aout + (size_t)row * NP + c0b) =
                        make_short4((short)v[0], (short)v[1], (short)v[2], (short)v[3]);
                } else {
#pragma unroll
                    for (int j = 0; j < 4; j++)
                        if (c0b + j < NP) aout[(size_t)row * NP + c0b + j] = (short)v[j];
                }
#pragma unroll
                for (int j = 0; j < 4; j++) {
                    s_loc[j] += v[j];
                    q_loc[j] += (unsigned)(v[j] * v[j]);
                }
            }
        }
        if (!FINAL) {
#pragma unroll
            for (int j = 0; j < 4; j++) {
                s_loc[j] += __shfl_down_sync(0xffffffffu, s_loc[j], 16);
                q_loc[j] += __shfl_down_sync(0xffffffffu, q_loc[j], 16);
            }
            if (lane < 16) {
                const int cc = col0 + lane * 4;
#pragma unroll
                for (int j = 0; j < 4; j++) {
                    atomicAdd(&s_sum[cc + j], s_loc[j]);
                    atomicAdd(&s_sq[cc + j], q_loc[j]);
                }
            }
        }
        __syncthreads();
    }

    if (!FINAL) {
        for (int idx = threadIdx.x; idx < 512; idx += 256) {
            atomicAdd(&g_sumA[SB][idx], s_sum[idx]);
            atomicAdd(&g_sum2A[SB][idx], (unsigned long long)s_sq[idx]);
        }
    }
}

__global__ void __launch_bounds__(TAIL_THREADS, 3)
tail_kernel(TailPtrs tp, float* __restrict__ fout, unsigned one, unsigned hi) {
    __shared__ unsigned As[64 * 17];
    __shared__ unsigned Bs[16 * 64];
    __shared__ int s_sum[512];
    __shared__ unsigned s_sq[512];
    __shared__ int s_thr[512];
    __shared__ unsigned char s_mode[512];

    thresh_smem(0, tp.gam[0], tp.bet[0], 500, s_thr, s_mode);
    pack_act_layer<500, 500, 16>(g_aout, g_act1, s_thr, s_mode);
    gsync();

    gemm_layer<400, 400, 500, 16, false, 1>(g_act1, g_wb[1], g_sb[1], g_aout, nullptr,
                                            one, hi, As, Bs, s_sum, s_sq);
    gsync();
    thresh_smem(1, tp.gam[1], tp.bet[1], 400, s_thr, s_mode);
    pack_act_layer<400, 400, 13>(g_aout, g_act0, s_thr, s_mode);
    gsync();

    gemm_layer<350, 352, 400, 13, false, 0>(g_act0, g_wb[2], g_sb[2], g_aout, nullptr,
                                            one, hi, As, Bs, s_sum, s_sq);
    gsync();
    thresh_smem(2, tp.gam[2], tp.bet[2], 350, s_thr, s_mode);
    pack_act_layer<350, 352, 11>(g_aout, g_act1, s_thr, s_mode);
    gsync();

    gemm_layer<300, 300, 350, 11, false, 1>(g_act1, g_wb[3], g_sb[3], g_aout, nullptr,
                                            one, hi, As, Bs, s_sum, s_sq);
    gsync();
    thresh_smem(3, tp.gam[3], tp.bet[3], 300, s_thr, s_mode);
    pack_act_layer<300, 300, 10>(g_aout, g_act0, s_thr, s_mode);
    gsync();

    gemm_layer<300, 300, 300, 10, false, 0>(g_act0, g_wb[4], g_sb[4], g_aout, nullptr,
                                            one, hi, As, Bs, s_sum, s_sq);
    gsync();
    thresh_smem(4, tp.gam[4], tp.bet[4], 300, s_thr, s_mode);
    pack_act_layer<300, 300, 10>(g_aout, g_act1, s_thr, s_mode);
    gsync();

    gemm_layer<35, 35, 300, 10, true, 0>(g_act1, g_wb[5], g_sb[5], nullptr, fout,
                                         one, hi, As, Bs, s_sum, s_sq);
}

// ---------------- host orchestration ----------------
extern "C" void kernel_launch(void* const* d_in, const int* in_sizes, int n_in,
                              void* d_out, int out_size) {
    (void)in_sizes; (void)n_in; (void)out_size;
    static const int LK[6]  = {4096, 500, 400, 350, 300, 300};
    static const int LN[6]  = {500, 400, 350, 300, 300, 35};
    static const int LKW[6] = {128, 16, 13, 11, 10, 10};

    const float* x = (const float*)d_in[0];
    const float* W[6]; const float* bb[6];
    TailPtrs tp;
    for (int l = 0; l < 5; l++) {
        W[l]      = (const float*)d_in[1 + 4 * l];
        bb[l]     = (const float*)d_in[2 + 4 * l];
        tp.gam[l] = (const float*)d_in[3 + 4 * l];
        tp.bet[l] = (const float*)d_in[4 + 4 * l];
    }
    W[5]  = (const float*)d_in[21];
    bb[5] = (const float*)d_in[22];

    signed char *xi8, *wi8;
    unsigned *wb;
    int *sb;
    short *aout;
    cudaGetSymbolAddress((void**)&xi8,  g_xi8);
    cudaGetSymbolAddress((void**)&wi8,  g_wi8);
    cudaGetSymbolAddress((void**)&wb,   g_wb);
    cudaGetSymbolAddress((void**)&sb,   g_sb);
    cudaGetSymbolAddress((void**)&aout, g_aout);

    BiasPtrs bp;
    for (int l = 0; l < 6; l++) bp.b[l] = bb[l];

    // regions: 0 = x (int8), 1 = W1 (int8), 2..6 = W2..W6 (bits)
    PackRegions pr;
    pr.src[0] = x; pr.dst[0] = xi8;
    pr.R[0] = MB; pr.C[0] = 4096; pr.KW[0] = 128; pr.G[0] = 32; pr.fmt[0] = 1;
    pr.src[1] = W[0]; pr.dst[1] = wi8;
    pr.R[1] = 500; pr.C[1] = 4096; pr.KW[1] = 128; pr.G[1] = 32; pr.fmt[1] = 1;
    for (int l = 1; l < 6; l++) {
        pr.src[1 + l] = W[l];
        pr.dst[1 + l] = wb + (size_t)l * 64000;
        pr.R[1 + l] = LN[l]; pr.C[1 + l] = LK[l]; pr.KW[1 + l] = LKW[l];
        pr.G[1 + l] = (LKW[l] + 3) / 4; pr.fmt[1 + l] = 0;
    }
    pr.total = 0;
    for (int r = 0; r < 7; r++) {
        pr.units[r] = (long long)pr.R[r] * pr.G[r];
        pr.total += pr.units[r];
    }

    // 1: prep
    prep_kernel<<<1, 512>>>(bp);
    // 2: pack everything
    pack_all_kernel<<<2048, 256>>>(pr);
    // 3: zero W1 pad rows
    wpad_kernel<<<12, 256>>>();
    // 4: layer-1 IMMA GEMM (ncu capture slot)
    {
        dim3 grid(4, MB / 128);
        gemm1_kernel<<<grid, 256>>>(xi8, wi8, sb, aout);
    }
    // 5: fused persistent tail
    tail_kernel<<<TAIL_CTAS, TAIL_THREADS>>>(tp, (float*)d_out, 1u, 65536u);
}

// round 15
// speedup vs baseline: 1.5502x; 1.5502x over previous
#include <cuda_runtime.h>
#include <cstdint>
#include <cstddef>

// Binarized 6-layer MLP, exact integer formulation.
//   dot(sign(a), sign(w)) = K - 2*popc(xor(bits_a, bits_w))
//   BN+Hardtanh+binarize folds to ONE integer threshold compare per column.
// Round 15: restore the proven 543us pipeline (tcgen05 blocked by toolchain,
// legacy mma.sync is emulation-rate); tail GEMM A-tile transposed [w][row]
// so the mainloop does 2x LDS.128 per w instead of 4 scalar LDS + 1 vector.

#define MB 16384
#define TAIL_CTAS 432          // 16 leaves x 27 arrivals
#define TAIL_THREADS 256

// ---------------- static device scratch ----------------
__device__ __align__(16) unsigned g_act0[MB * 128];        // 8 MB
__device__ __align__(16) unsigned g_act1[MB * 16];         // 1 MB
__device__ __align__(16) unsigned g_wb[6][64000];
__device__ int                    g_sb[6][512];
__device__ __align__(16) short    g_aout[(size_t)MB * 512];
__device__ int                    g_sumA[2][512];          // double-buffered stats
__device__ unsigned long long     g_sum2A[2][512];

struct __align__(128) LeafCtr { unsigned v; unsigned pad[31]; };
__device__ LeafCtr                g_leaf[16];
__device__ unsigned               g_root;
__device__ volatile unsigned      g_gen;

// ---------------- one-shot prep ----------------
struct BiasPtrs { const float* b[6]; };

__global__ void prep_kernel(BiasPtrs bp) {
    int j = threadIdx.x;   // 512 threads
    static const int LNc[6] = {500, 400, 350, 300, 300, 35};
#pragma unroll
    for (int l = 0; l < 6; l++)
        if (j < LNc[l]) g_sb[l][j] = (bp.b[l][j] < 0.0f) ? -1 : 1;
    g_sumA[0][j] = 0;  g_sumA[1][j] = 0;
    g_sum2A[0][j] = 0ull; g_sum2A[1][j] = 0ull;
    if (j < 16) g_leaf[j].v = 0u;
    if (j == 0) { g_root = 0u; g_gen = 0u; }
}

// ---------------- fused sign-pack: x (fast float4+shfl) + weights (scalar) ----------------
struct PackRegions {
    const float* src[7];
    unsigned*    dst[7];
    int R[7], C[7], KW[7], G[7];
    long long units[7];
    long long total;
};

__global__ void pack_all_kernel(PackRegions pr) {
    const int lane = threadIdx.x & 31;
    const int wid  = threadIdx.x >> 5;
    const long long stride = (long long)gridDim.x * (blockDim.x / 32);
    for (long long gw = (long long)blockIdx.x * (blockDim.x / 32) + wid;
         gw < pr.total; gw += stride) {
        long long u = gw;
        int r = 0;
        while (u >= pr.units[r]) { u -= pr.units[r]; r++; }
        const int G = pr.G[r], C = pr.C[r], KW = pr.KW[r];
        const int row = (int)(u / G);
        const int g   = (int)(u - (long long)row * G);   // group of 4 words
        if (r == 0) {
            // fast path: x, C=4096. 128 cols per unit; lane loads float4.
            const float4 v = *(const float4*)(pr.src[0] + (size_t)row * 4096
                                              + g * 128 + lane * 4);
            unsigned nib = (v.x < 0.0f ? 1u : 0u) | (v.y < 0.0f ? 2u : 0u)
                         | (v.z < 0.0f ? 4u : 0u) | (v.w < 0.0f ? 8u : 0u);
            unsigned t = nib | (__shfl_xor_sync(0xffffffffu, nib, 1) << 4);
            t |= __shfl_xor_sync(0xffffffffu, t, 2) << 8;
            t |= __shfl_xor_sync(0xffffffffu, t, 4) << 16;
            if ((lane & 7) == 0)
                pr.dst[0][(size_t)row * 128 + g * 4 + (lane >> 3)] = t;
        } else {
            const int w0 = g * 4;
            const float* src = pr.src[r] + (size_t)row * C;
            float v[4];
#pragma unroll
            for (int k = 0; k < 4; k++) {
                int col = (w0 + k) * 32 + lane;
                v[k] = (w0 + k < KW && col < C) ? src[col] : 0.0f;
            }
#pragma unroll
            for (int k = 0; k < 4; k++) {
                unsigned m = __ballot_sync(0xffffffffu, v[k] < 0.0f);
                if (lane == 0 && w0 + k < KW)
                    pr.dst[r][(size_t)row * KW + w0 + k] = m;
            }
        }
    }
}

// ---------------- specialized layer-1 GEMM: M=16384, N=500, KW=128 ----------------
#define L1KW 128
#define L1N  500
#define APAD 132
#define BPAD 68

__global__ void __launch_bounds__(256, 4)
gemm1_kernel(const unsigned* __restrict__ A, const unsigned* __restrict__ B,
             const int* __restrict__ sb, short* __restrict__ out,
             unsigned one, unsigned hi) {
    __shared__ unsigned As[2][16][APAD];
    __shared__ unsigned Bs[2][16][BPAD];

    const int tid = threadIdx.x;
    const int tx = tid & 15;
    const int ty = tid >> 4;
    const int row0 = blockIdx.y * 128;
    const int col0 = blockIdx.x * 64;

    unsigned acc[8][2];
#pragma unroll
    for (int i = 0; i < 8; i++) { acc[i][0] = 0u; acc[i][1] = 0u; }

    const int ra = tid >> 2;
    const int wq = tid & 3;

    uint4 pa0, pa1, pb;
    {
        pa0 = *(const uint4*)(A + (size_t)(row0 + ra) * L1KW + wq * 4);
        pa1 = *(const uint4*)(A + (size_t)(row0 + ra + 64) * L1KW + wq * 4);
        int cb = col0 + ra;
        pb = (cb < L1N) ? *(const uint4*)(B + (size_t)cb * L1KW + wq * 4)
                        : make_uint4(0, 0, 0, 0);
        As[0][wq * 4 + 0][ra] = pa0.x; As[0][wq * 4 + 1][ra] = pa0.y;
        As[0][wq * 4 + 2][ra] = pa0.z; As[0][wq * 4 + 3][ra] = pa0.w;
        As[0][wq * 4 + 0][ra + 64] = pa1.x; As[0][wq * 4 + 1][ra + 64] = pa1.y;
        As[0][wq * 4 + 2][ra + 64] = pa1.z; As[0][wq * 4 + 3][ra + 64] = pa1.w;
        Bs[0][wq * 4 + 0][ra] = pb.x; Bs[0][wq * 4 + 1][ra] = pb.y;
        Bs[0][wq * 4 + 2][ra] = pb.z; Bs[0][wq * 4 + 3][ra] = pb.w;
    }
    __syncthreads();

#pragma unroll 1
    for (int ch = 0; ch < 8; ch++) {
        const int buf = ch & 1;
        if (ch < 7) {
            const int w0 = (ch + 1) * 16;
            pa0 = *(const uint4*)(A + (size_t)(row0 + ra) * L1KW + w0 + wq * 4);
            pa1 = *(const uint4*)(A + (size_t)(row0 + ra + 64) * L1KW + w0 + wq * 4);
            int cb = col0 + ra;
            pb = (cb < L1N) ? *(const uint4*)(B + (size_t)cb * L1KW + w0 + wq * 4)
                            : make_uint4(0, 0, 0, 0);
        }
#pragma unroll
        for (int w = 0; w < 16; w++) {
            uint4 av0 = *(const uint4*)&As[buf][w][ty * 8];
            uint4 av1 = *(const uint4*)&As[buf][w][ty * 8 + 4];
            uint4 bv  = *(const uint4*)&Bs[buf][w][tx * 4];
            unsigned a[8] = {av0.x, av0.y, av0.z, av0.w, av1.x, av1.y, av1.z, av1.w};
#pragma unroll
            for (int i = 0; i < 8; i++) {
                acc[i][0] += __popc(a[i] ^ bv.x) * one + __popc(a[i] ^ bv.y) * hi;
                acc[i][1] += __popc(a[i] ^ bv.z) * one + __popc(a[i] ^ bv.w) * hi;
            }
        }
        if (ch < 7) {
            const int nb = buf ^ 1;
            As[nb][wq * 4 + 0][ra] = pa0.x; As[nb][wq * 4 + 1][ra] = pa0.y;
            As[nb][wq * 4 + 2][ra] = pa0.z; As[nb][wq * 4 + 3][ra] = pa0.w;
            As[nb][wq * 4 + 0][ra + 64] = pa1.x; As[nb][wq * 4 + 1][ra + 64] = pa1.y;
            As[nb][wq * 4 + 2][ra + 64] = pa1.z; As[nb][wq * 4 + 3][ra + 64] = pa1.w;
            Bs[nb][wq * 4 + 0][ra] = pb.x; Bs[nb][wq * 4 + 1][ra] = pb.y;
            Bs[nb][wq * 4 + 2][ra] = pb.z; Bs[nb][wq * 4 + 3][ra] = pb.w;
        }
        __syncthreads();
    }

    int sbr[4];
#pragma unroll
    for (int j = 0; j < 4; j++) {
        int col = col0 + tx * 4 + j;
        sbr[j] = (col < L1N) ? sb[col] : 0;
    }
    int s_loc[4];
    unsigned q_loc[4];
#pragma unroll
    for (int j = 0; j < 4; j++) { s_loc[j] = 0; q_loc[j] = 0; }
    const int c0b = col0 + tx * 4;
#pragma unroll
    for (int i = 0; i < 8; i++) {
        int row = row0 + ty * 8 + i;
        int v[4];
#pragma unroll
        for (int jj = 0; jj < 2; jj++) {
            v[jj * 2 + 0] = 4096 - 2 * (int)(acc[i][jj] & 0xFFFFu) + sbr[jj * 2 + 0];
            v[jj * 2 + 1] = 4096 - 2 * (int)(acc[i][jj] >> 16)     + sbr[jj * 2 + 1];
        }
        if (c0b + 3 < L1N) {
            *(short4*)(out + (size_t)row * L1N + c0b) =
                make_short4((short)v[0], (short)v[1], (short)v[2], (short)v[3]);
        } else {
#pragma unroll
            for (int j = 0; j < 4; j++)
                if (c0b + j < L1N) out[(size_t)row * L1N + c0b + j] = (short)v[j];
        }
#pragma unroll
        for (int j = 0; j < 4; j++) {
            s_loc[j] += v[j];
            q_loc[j] += (unsigned)(v[j] * v[j]);
        }
    }
    int* Ssum = (int*)&As[0][0][0];
    unsigned* Ssq = (unsigned*)&Bs[0][0][0];
#pragma unroll
    for (int j = 0; j < 4; j++) {
        Ssum[ty * 64 + tx * 4 + j] = s_loc[j];
        Ssq [ty * 64 + tx * 4 + j] = q_loc[j];
    }
    __syncthreads();
    for (int off = 8; off >= 1; off >>= 1) {
        if (ty < off) {
#pragma unroll
            for (int j = 0; j < 4; j++) {
                int c = tx * 4 + j;
                Ssum[ty * 64 + c] += Ssum[(ty + off) * 64 + c];
                Ssq [ty * 64 + c] += Ssq [(ty + off) * 64 + c];
            }
        }
        __syncthreads();
    }
    if (ty == 0) {
#pragma unroll
        for (int j = 0; j < 4; j++) {
            int col = col0 + tx * 4 + j;
            if (col < L1N) {
                atomicAdd(&g_sumA[0][col], Ssum[tx * 4 + j]);
                atomicAdd(&g_sum2A[0][col], (unsigned long long)Ssq[tx * 4 + j]);
            }
        }
    }
}

// ================= persistent tail kernel =================
struct TailPtrs { const float* gam[5]; const float* bet[5]; };

__device__ __forceinline__ void gsync() {
    __syncthreads();
    if (threadIdx.x == 0) {
        __threadfence();
        unsigned gen = g_gen;
        int leaf = blockIdx.x & 15;
        unsigned t = atomicAdd(&g_leaf[leaf].v, 1u);
        if (t == (TAIL_CTAS / 16 - 1)) {
            g_leaf[leaf].v = 0u;
            unsigned r = atomicAdd(&g_root, 1u);
            if (r == 15u) {
                g_root = 0u;
                __threadfence();
                g_gen = gen + 1u;
            } else {
                while (g_gen == gen) __nanosleep(64);
            }
        } else {
            while (g_gen == gen) __nanosleep(64);
        }
        __threadfence();
    }
    __syncthreads();
}

__device__ void thresh_smem(int l, const float* __restrict__ gam,
                            const float* __restrict__ bet, int N,
                            int* s_thr, unsigned char* s_mode) {
    int buf = l & 1, nxt = buf ^ 1;
    for (int j = threadIdx.x; j < 512; j += TAIL_THREADS) {
        g_sumA[nxt][j] = 0; g_sum2A[nxt][j] = 0ull;
    }
    for (int j = threadIdx.x; j < N; j += TAIL_THREADS) {
        double mean = (double)g_sumA[buf][j] / 16384.0;
        double var  = (double)(long long)g_sum2A[buf][j] / 16384.0 - mean * mean;
        double invstd = 1.0 / sqrt(var + 1e-5);
        double scale = invstd * (double)gam[j];
        double shift = (double)bet[j];
        int thr, mode;
        if (scale > 0.0) {
            double t = fmin(fmax(mean - shift / scale, -1.0e9), 1.0e9);
            thr = (int)ceil(t);  mode = 0;
        } else if (scale < 0.0) {
            double t = fmin(fmax(mean - shift / scale, -1.0e9), 1.0e9);
            thr = (int)floor(t); mode = 1;
        } else {
            mode = 0;
            thr = (shift < 0.0) ? 2147483647 : (-2147483647 - 1);
        }
        s_thr[j] = thr;
        s_mode[j] = (unsigned char)mode;
    }
    __syncthreads();
}

// pack next-layer sign bits: one row per warp iteration, loads batched 8-wide.
template <int C, int NP, int KW>
__device__ void pack_act_layer(const short* __restrict__ a, unsigned* __restrict__ dst,
                               const int* s_thr, const unsigned char* s_mode) {
    const int wid = threadIdx.x >> 5, lane = threadIdx.x & 31;
    const int gw = blockIdx.x * (TAIL_THREADS / 32) + wid;
    const int total = TAIL_CTAS * (TAIL_THREADS / 32);
    for (int row = gw; row < MB; row += total) {
        const short* ar = a + (size_t)row * NP;
        unsigned* dr = dst + (size_t)row * KW;
#pragma unroll
        for (int w0 = 0; w0 < KW; w0 += 8) {
            const int nb = (KW - w0 < 8) ? (KW - w0) : 8;
            int v[8];
#pragma unroll
            for (int k = 0; k < 8; k++) {
                if (k < nb) {
                    int col = (w0 + k) * 32 + lane;
                    v[k] = (col < C) ? (int)ar[col] : 0;
                }
            }
            unsigned m[8];
#pragma unroll
            for (int k = 0; k < 8; k++) {
                if (k < nb) {
                    int col = (w0 + k) * 32 + lane;
                    bool neg = false;
                    if (col < C) {
                        int thr = s_thr[col];
                        neg = s_mode[col] ? (v[k] > thr) : (v[k] < thr);
                    }
                    m[k] = __ballot_sync(0xffffffffu, neg);
                }
            }
            if (lane == 0) {
#pragma unroll
                for (int k = 0; k < 8; k++)
                    if (k < nb) dr[w0 + k] = m[k];
            }
        }
    }
}

// tail GEMM: 64x64 tiles, 2 syncs/tile, packed dual-16-bit accs.
// As TRANSPOSED to [w][row] stride 68 -> mainloop = 2x LDS.128 per w
// (A: 4 contiguous rows, B: 4 contiguous cols) instead of 4 scalar + 1 vector.
template <int N, int NP, int K, int KW, bool FINAL, int SB>
__device__ void gemm_layer(const unsigned* __restrict__ abits, const unsigned* __restrict__ bbits,
                           const int* __restrict__ sb, short* __restrict__ aout,
                           float* __restrict__ fout, unsigned one, unsigned hi,
                           unsigned* As /*16*68=1088*/, unsigned* Bs /*16*64*/,
                           int* s_sum, unsigned* s_sq) {
    const int tx = threadIdx.x & 15;
    const int ty = threadIdx.x >> 4;
    const int lane = threadIdx.x & 31;
    const int ct = (N + 63) / 64;
    const int ntiles = (MB / 64) * ct;

    if (!FINAL) {
        for (int idx = threadIdx.x; idx < 512; idx += 256) { s_sum[idx] = 0; s_sq[idx] = 0u; }
    }
    __syncthreads();

    for (int t = blockIdx.x; t < ntiles; t += TAIL_CTAS) {
        const int row0 = (t / ct) * 64;
        const int col0 = (t % ct) * 64;

        unsigned acc[4][2];
#pragma unroll
        for (int i = 0; i < 4; i++) { acc[i][0] = 0u; acc[i][1] = 0u; }

        // A fill: transposed [w][row], LDG coalesced (w fastest within row)
        for (int idx = threadIdx.x; idx < 64 * 16; idx += 256) {
            int r = idx >> 4, w = idx & 15;
            As[w * 68 + r] = (w < KW) ? abits[(size_t)(row0 + r) * KW + w] : 0u;
        }
        for (int idx = threadIdx.x; idx < 64 * 16; idx += 256) {
            int c = idx & 63, w = idx >> 6;
            int col = col0 + c;
            Bs[w * 64 + c] = (col < N && w < KW) ? bbits[(size_t)col * KW + w] : 0u;
        }
        __syncthreads();

#pragma unroll
        for (int w = 0; w < KW; w++) {
            uint4 av = *(const uint4*)&As[w * 68 + ty * 4];
            uint4 bv = *(const uint4*)&Bs[w * 64 + tx * 4];
            unsigned a[4] = {av.x, av.y, av.z, av.w};
#pragma unroll
            for (int i = 0; i < 4; i++) {
                acc[i][0] += __popc(a[i] ^ bv.x) * one + __popc(a[i] ^ bv.y) * hi;
                acc[i][1] += __popc(a[i] ^ bv.z) * one + __popc(a[i] ^ bv.w) * hi;
            }
        }

        int sbr[4];
        const int c0b = col0 + tx * 4;
#pragma unroll
        for (int j = 0; j < 4; j++) sbr[j] = sb[c0b + j];

        int s_loc[4];
        unsigned q_loc[4];
#pragma unroll
        for (int j = 0; j < 4; j++) { s_loc[j] = 0; q_loc[j] = 0; }

#pragma unroll
        for (int i = 0; i < 4; i++) {
            int row = row0 + ty * 4 + i;
            int v[4];
#pragma unroll
            for (int jj = 0; jj < 2; jj++) {
                v[jj * 2 + 0] = K - 2 * (int)(acc[i][jj] & 0xFFFFu) + sbr[jj * 2 + 0];
                v[jj * 2 + 1] = K - 2 * (int)(acc[i][jj] >> 16)     + sbr[jj * 2 + 1];
            }
            if (FINAL) {
#pragma unroll
                for (int j = 0; j < 4; j++)
                    if (c0b + j < N) fout[(size_t)row * N + c0b + j] = (float)v[j];
            } else {
                if (c0b + 3 < NP) {
                    *(short4*)(aout + (size_t)row * NP + c0b) =
                        make_short4((short)v[0], (short)v[1], (short)v[2], (short)v[3]);
                } else {
#pragma unroll
                    for (int j = 0; j < 4; j++)
                        if (c0b + j < NP) aout[(size_t)row * NP + c0b + j] = (short)v[j];
                }
#pragma unroll
                for (int j = 0; j < 4; j++) {
                    s_loc[j] += v[j];
                    q_loc[j] += (unsigned)(v[j] * v[j]);
                }
            }
        }
        if (!FINAL) {
#pragma unroll
            for (int j = 0; j < 4; j++) {
                s_loc[j] += __shfl_down_sync(0xffffffffu, s_loc[j], 16);
                q_loc[j] += __shfl_down_sync(0xffffffffu, q_loc[j], 16);
            }
            if (lane < 16) {
                const int cc = col0 + lane * 4;
#pragma unroll
                for (int j = 0; j < 4; j++) {
                    atomicAdd(&s_sum[cc + j], s_loc[j]);
                    atomicAdd(&s_sq[cc + j], q_loc[j]);
                }
            }
        }
        __syncthreads();   // protect As/Bs for next fill
    }

    if (!FINAL) {
        for (int idx = threadIdx.x; idx < 512; idx += 256) {
            atomicAdd(&g_sumA[SB][idx], s_sum[idx]);
            atomicAdd(&g_sum2A[SB][idx], (unsigned long long)s_sq[idx]);
        }
    }
}

__global__ void __launch_bounds__(TAIL_THREADS, 3)
tail_kernel(TailPtrs tp, float* __restrict__ fout, unsigned one, unsigned hi) {
    __shared__ unsigned As[16 * 68];   // 1088 words (same size as 64*17)
    __shared__ unsigned Bs[16 * 64];
    __shared__ int s_sum[512];
    __shared__ unsigned s_sq[512];
    __shared__ int s_thr[512];
    __shared__ unsigned char s_mode[512];

    thresh_smem(0, tp.gam[0], tp.bet[0], 500, s_thr, s_mode);
    pack_act_layer<500, 500, 16>(g_aout, g_act1, s_thr, s_mode);
    gsync();

    gemm_layer<400, 400, 500, 16, false, 1>(g_act1, g_wb[1], g_sb[1], g_aout, nullptr,
                                            one, hi, As, Bs, s_sum, s_sq);
    gsync();
    thresh_smem(1, tp.gam[1], tp.bet[1], 400, s_thr, s_mode);
    pack_act_layer<400, 400, 13>(g_aout, g_act0, s_thr, s_mode);
    gsync();

    gemm_layer<350, 352, 400, 13, false, 0>(g_act0, g_wb[2], g_sb[2], g_aout, nullptr,
                                            one, hi, As, Bs, s_sum, s_sq);
    gsync();
    thresh_smem(2, tp.gam[2], tp.bet[2], 350, s_thr, s_mode);
    pack_act_layer<350, 352, 11>(g_aout, g_act1, s_thr, s_mode);
    gsync();

    gemm_layer<300, 300, 350, 11, false, 1>(g_act1, g_wb[3], g_sb[3], g_aout, nullptr,
                                            one, hi, As, Bs, s_sum, s_sq);
    gsync();
    thresh_smem(3, tp.gam[3], tp.bet[3], 300, s_thr, s_mode);
    pack_act_layer<300, 300, 10>(g_aout, g_act0, s_thr, s_mode);
    gsync();

    gemm_layer<300, 300, 300, 10, false, 0>(g_act0, g_wb[4], g_sb[4], g_aout, nullptr,
                                            one, hi, As, Bs, s_sum, s_sq);
    gsync();
    thresh_smem(4, tp.gam[4], tp.bet[4], 300, s_thr, s_mode);
    pack_act_layer<300, 300, 10>(g_aout, g_act1, s_thr, s_mode);
    gsync();

    gemm_layer<35, 35, 300, 10, true, 0>(g_act1, g_wb[5], g_sb[5], nullptr, fout,
                                         one, hi, As, Bs, s_sum, s_sq);
}

// ---------------- host orchestration ----------------
extern "C" void kernel_launch(void* const* d_in, const int* in_sizes, int n_in,
                              void* d_out, int out_size) {
    (void)in_sizes; (void)n_in; (void)out_size;
    static const int LK[6]  = {4096, 500, 400, 350, 300, 300};
    static const int LN[6]  = {500, 400, 350, 300, 300, 35};
    static const int LKW[6] = {128, 16, 13, 11, 10, 10};

    const float* x = (const float*)d_in[0];
    const float* W[6]; const float* bb[6];
    TailPtrs tp;
    for (int l = 0; l < 5; l++) {
        W[l]      = (const float*)d_in[1 + 4 * l];
        bb[l]     = (const float*)d_in[2 + 4 * l];
        tp.gam[l] = (const float*)d_in[3 + 4 * l];
        tp.bet[l] = (const float*)d_in[4 + 4 * l];
    }
    W[5]  = (const float*)d_in[21];
    bb[5] = (const float*)d_in[22];

    unsigned *act0, *wb;
    int *sb;
    short *aout;
    cudaGetSymbolAddress((void**)&act0, g_act0);
    cudaGetSymbolAddress((void**)&wb,   g_wb);
    cudaGetSymbolAddress((void**)&sb,   g_sb);
    cudaGetSymbolAddress((void**)&aout, g_aout);

    BiasPtrs bp;
    for (int l = 0; l < 6; l++) bp.b[l] = bb[l];

    PackRegions pr;
    pr.src[0] = x; pr.dst[0] = act0;
    pr.R[0] = MB; pr.C[0] = 4096; pr.KW[0] = 128; pr.G[0] = 32;
    for (int l = 0; l < 6; l++) {
        pr.src[1 + l] = W[l];
        pr.dst[1 + l] = wb + (size_t)l * 64000;
        pr.R[1 + l] = LN[l]; pr.C[1 + l] = LK[l]; pr.KW[1 + l] = LKW[l];
        pr.G[1 + l] = (LKW[l] + 3) / 4;
    }
    pr.total = 0;
    for (int r = 0; r < 7; r++) {
        pr.units[r] = (long long)pr.R[r] * pr.G[r];
        pr.total += pr.units[r];
    }

    // 1: prep
    prep_kernel<<<1, 512>>>(bp);
    // 2: all sign packing
    pack_all_kernel<<<2048, 256>>>(pr);
    // 3: gemm1 + fused stats
    {
        dim3 grid(8, MB / 128);
        gemm1_kernel<<<grid, 256>>>(act0, wb, sb, aout, 1u, 65536u);
    }
    // 4: fused persistent tail (ncu capture slot)
    tail_kernel<<<TAIL_CTAS, TAIL_THREADS>>>(tp, (float*)d_out, 1u, 65536u);
}

// round 17
// speedup vs baseline: 1.5847x; 1.0223x over previous
#include <cuda_runtime.h>
#include <cstdint>
#include <cstddef>

// Binarized 6-layer MLP, exact integer formulation.
//   dot(sign(a), sign(w)) = K - 2*popc(xor(bits_a, bits_w))
//   BN+Hardtanh+binarize folds to ONE integer threshold compare per column.
// Round 16: tail GEMM software-pipelined across tiles — next tile's A/B are
// LDG-prefetched into registers during the current tile's mainloop, hiding
// the ~600-cycle fill latency that dominated the per-tile serial time.

#define MB 16384
#define TAIL_CTAS 432          // 16 leaves x 27 arrivals
#define TAIL_THREADS 256

// ---------------- static device scratch ----------------
__device__ __align__(16) unsigned g_act0[MB * 128];        // 8 MB
__device__ __align__(16) unsigned g_act1[MB * 16];         // 1 MB
__device__ __align__(16) unsigned g_wb[6][64000];
__device__ int                    g_sb[6][512];
__device__ __align__(16) short    g_aout[(size_t)MB * 512];
__device__ int                    g_sumA[2][512];          // double-buffered stats
__device__ unsigned long long     g_sum2A[2][512];

struct __align__(128) LeafCtr { unsigned v; unsigned pad[31]; };
__device__ LeafCtr                g_leaf[16];
__device__ unsigned               g_root;
__device__ volatile unsigned      g_gen;

// ---------------- one-shot prep ----------------
struct BiasPtrs { const float* b[6]; };

__global__ void prep_kernel(BiasPtrs bp) {
    int j = threadIdx.x;   // 512 threads
    static const int LNc[6] = {500, 400, 350, 300, 300, 35};
#pragma unroll
    for (int l = 0; l < 6; l++)
        if (j < LNc[l]) g_sb[l][j] = (bp.b[l][j] < 0.0f) ? -1 : 1;
    g_sumA[0][j] = 0;  g_sumA[1][j] = 0;
    g_sum2A[0][j] = 0ull; g_sum2A[1][j] = 0ull;
    if (j < 16) g_leaf[j].v = 0u;
    if (j == 0) { g_root = 0u; g_gen = 0u; }
}

// ---------------- fused sign-pack: x (fast float4+shfl) + weights (scalar) ----------------
struct PackRegions {
    const float* src[7];
    unsigned*    dst[7];
    int R[7], C[7], KW[7], G[7];
    long long units[7];
    long long total;
};

__global__ void pack_all_kernel(PackRegions pr) {
    const int lane = threadIdx.x & 31;
    const int wid  = threadIdx.x >> 5;
    const long long stride = (long long)gridDim.x * (blockDim.x / 32);
    for (long long gw = (long long)blockIdx.x * (blockDim.x / 32) + wid;
         gw < pr.total; gw += stride) {
        long long u = gw;
        int r = 0;
        while (u >= pr.units[r]) { u -= pr.units[r]; r++; }
        const int G = pr.G[r], C = pr.C[r], KW = pr.KW[r];
        const int row = (int)(u / G);
        const int g   = (int)(u - (long long)row * G);   // group of 4 words
        if (r == 0) {
            // fast path: x, C=4096. 128 cols per unit; lane loads float4.
            const float4 v = *(const float4*)(pr.src[0] + (size_t)row * 4096
                                              + g * 128 + lane * 4);
            unsigned nib = (v.x < 0.0f ? 1u : 0u) | (v.y < 0.0f ? 2u : 0u)
                         | (v.z < 0.0f ? 4u : 0u) | (v.w < 0.0f ? 8u : 0u);
            unsigned t = nib | (__shfl_xor_sync(0xffffffffu, nib, 1) << 4);
            t |= __shfl_xor_sync(0xffffffffu, t, 2) << 8;
            t |= __shfl_xor_sync(0xffffffffu, t, 4) << 16;
            if ((lane & 7) == 0)
                pr.dst[0][(size_t)row * 128 + g * 4 + (lane >> 3)] = t;
        } else {
            const int w0 = g * 4;
            const float* src = pr.src[r] + (size_t)row * C;
            float v[4];
#pragma unroll
            for (int k = 0; k < 4; k++) {
                int col = (w0 + k) * 32 + lane;
                v[k] = (w0 + k < KW && col < C) ? src[col] : 0.0f;
            }
#pragma unroll
            for (int k = 0; k < 4; k++) {
                unsigned m = __ballot_sync(0xffffffffu, v[k] < 0.0f);
                if (lane == 0 && w0 + k < KW)
                    pr.dst[r][(size_t)row * KW + w0 + k] = m;
            }
        }
    }
}

// ---------------- specialized layer-1 GEMM: M=16384, N=500, KW=128 ----------------
#define L1KW 128
#define L1N  500
#define APAD 132
#define BPAD 68

__global__ void __launch_bounds__(256, 4)
gemm1_kernel(const unsigned* __restrict__ A, const unsigned* __restrict__ B,
             const int* __restrict__ sb, short* __restrict__ out,
             unsigned one, unsigned hi) {
    __shared__ unsigned As[2][16][APAD];
    __shared__ unsigned Bs[2][16][BPAD];

    const int tid = threadIdx.x;
    const int tx = tid & 15;
    const int ty = tid >> 4;
    const int row0 = blockIdx.y * 128;
    const int col0 = blockIdx.x * 64;

    unsigned acc[8][2];
#pragma unroll
    for (int i = 0; i < 8; i++) { acc[i][0] = 0u; acc[i][1] = 0u; }

    const int ra = tid >> 2;
    const int wq = tid & 3;

    uint4 pa0, pa1, pb;
    {
        pa0 = *(const uint4*)(A + (size_t)(row0 + ra) * L1KW + wq * 4);
        pa1 = *(const uint4*)(A + (size_t)(row0 + ra + 64) * L1KW + wq * 4);
        int cb = col0 + ra;
        pb = (cb < L1N) ? *(const uint4*)(B + (size_t)cb * L1KW + wq * 4)
                        : make_uint4(0, 0, 0, 0);
        As[0][wq * 4 + 0][ra] = pa0.x; As[0][wq * 4 + 1][ra] = pa0.y;
        As[0][wq * 4 + 2][ra] = pa0.z; As[0][wq * 4 + 3][ra] = pa0.w;
        As[0][wq * 4 + 0][ra + 64] = pa1.x; As[0][wq * 4 + 1][ra + 64] = pa1.y;
        As[0][wq * 4 + 2][ra + 64] = pa1.z; As[0][wq * 4 + 3][ra + 64] = pa1.w;
        Bs[0][wq * 4 + 0][ra] = pb.x; Bs[0][wq * 4 + 1][ra] = pb.y;
        Bs[0][wq * 4 + 2][ra] = pb.z; Bs[0][wq * 4 + 3][ra] = pb.w;
    }
    __syncthreads();

#pragma unroll 1
    for (int ch = 0; ch < 8; ch++) {
        const int buf = ch & 1;
        if (ch < 7) {
            const int w0 = (ch + 1) * 16;
            pa0 = *(const uint4*)(A + (size_t)(row0 + ra) * L1KW + w0 + wq * 4);
            pa1 = *(const uint4*)(A + (size_t)(row0 + ra + 64) * L1KW + w0 + wq * 4);
            int cb = col0 + ra;
            pb = (cb < L1N) ? *(const uint4*)(B + (size_t)cb * L1KW + w0 + wq * 4)
                            : make_uint4(0, 0, 0, 0);
        }
#pragma unroll
        for (int w = 0; w < 16; w++) {
            uint4 av0 = *(const uint4*)&As[buf][w][ty * 8];
            uint4 av1 = *(const uint4*)&As[buf][w][ty * 8 + 4];
            uint4 bv  = *(const uint4*)&Bs[buf][w][tx * 4];
            unsigned a[8] = {av0.x, av0.y, av0.z, av0.w, av1.x, av1.y, av1.z, av1.w};
#pragma unroll
            for (int i = 0; i < 8; i++) {
                acc[i][0] += __popc(a[i] ^ bv.x) * one + __popc(a[i] ^ bv.y) * hi;
                acc[i][1] += __popc(a[i] ^ bv.z) * one + __popc(a[i] ^ bv.w) * hi;
            }
        }
        if (ch < 7) {
            const int nb = buf ^ 1;
            As[nb][wq * 4 + 0][ra] = pa0.x; As[nb][wq * 4 + 1][ra] = pa0.y;
            As[nb][wq * 4 + 2][ra] = pa0.z; As[nb][wq * 4 + 3][ra] = pa0.w;
            As[nb][wq * 4 + 0][ra + 64] = pa1.x; As[nb][wq * 4 + 1][ra + 64] = pa1.y;
            As[nb][wq * 4 + 2][ra + 64] = pa1.z; As[nb][wq * 4 + 3][ra + 64] = pa1.w;
            Bs[nb][wq * 4 + 0][ra] = pb.x; Bs[nb][wq * 4 + 1][ra] = pb.y;
            Bs[nb][wq * 4 + 2][ra] = pb.z; Bs[nb][wq * 4 + 3][ra] = pb.w;
        }
        __syncthreads();
    }

    int sbr[4];
#pragma unroll
    for (int j = 0; j < 4; j++) {
        int col = col0 + tx * 4 + j;
        sbr[j] = (col < L1N) ? sb[col] : 0;
    }
    int s_loc[4];
    unsigned q_loc[4];
#pragma unroll
    for (int j = 0; j < 4; j++) { s_loc[j] = 0; q_loc[j] = 0; }
    const int c0b = col0 + tx * 4;
#pragma unroll
    for (int i = 0; i < 8; i++) {
        int row = row0 + ty * 8 + i;
        int v[4];
#pragma unroll
        for (int jj = 0; jj < 2; jj++) {
            v[jj * 2 + 0] = 4096 - 2 * (int)(acc[i][jj] & 0xFFFFu) + sbr[jj * 2 + 0];
            v[jj * 2 + 1] = 4096 - 2 * (int)(acc[i][jj] >> 16)     + sbr[jj * 2 + 1];
        }
        if (c0b + 3 < L1N) {
            *(short4*)(out + (size_t)row * L1N + c0b) =
                make_short4((short)v[0], (short)v[1], (short)v[2], (short)v[3]);
        } else {
#pragma unroll
            for (int j = 0; j < 4; j++)
                if (c0b + j < L1N) out[(size_t)row * L1N + c0b + j] = (short)v[j];
        }
#pragma unroll
        for (int j = 0; j < 4; j++) {
            s_loc[j] += v[j];
            q_loc[j] += (unsigned)(v[j] * v[j]);
        }
    }
    int* Ssum = (int*)&As[0][0][0];
    unsigned* Ssq = (unsigned*)&Bs[0][0][0];
#pragma unroll
    for (int j = 0; j < 4; j++) {
        Ssum[ty * 64 + tx * 4 + j] = s_loc[j];
        Ssq [ty * 64 + tx * 4 + j] = q_loc[j];
    }
    __syncthreads();
    for (int off = 8; off >= 1; off >>= 1) {
        if (ty < off) {
#pragma unroll
            for (int j = 0; j < 4; j++) {
                int c = tx * 4 + j;
                Ssum[ty * 64 + c] += Ssum[(ty + off) * 64 + c];
                Ssq [ty * 64 + c] += Ssq [(ty + off) * 64 + c];
            }
        }
        __syncthreads();
    }
    if (ty == 0) {
#pragma unroll
        for (int j = 0; j < 4; j++) {
            int col = col0 + tx * 4 + j;
            if (col < L1N) {
                atomicAdd(&g_sumA[0][col], Ssum[tx * 4 + j]);
                atomicAdd(&g_sum2A[0][col], (unsigned long long)Ssq[tx * 4 + j]);
            }
        }
    }
}

// ================= persistent tail kernel =================
struct TailPtrs { const float* gam[5]; const float* bet[5]; };

__device__ __forceinline__ void gsync() {
    __syncthreads();
    if (threadIdx.x == 0) {
        __threadfence();
        unsigned gen = g_gen;
        int leaf = blockIdx.x & 15;
        unsigned t = atomicAdd(&g_leaf[leaf].v, 1u);
        if (t == (TAIL_CTAS / 16 - 1)) {
            g_leaf[leaf].v = 0u;
            unsigned r = atomicAdd(&g_root, 1u);
            if (r == 15u) {
                g_root = 0u;
                __threadfence();
                g_gen = gen + 1u;
            } else {
                while (g_gen == gen) __nanosleep(64);
            }
        } else {
            while (g_gen == gen) __nanosleep(64);
        }
        __threadfence();
    }
    __syncthreads();
}

__device__ void thresh_smem(int l, const float* __restrict__ gam,
                            const float* __restrict__ bet, int N,
                            int* s_thr, unsigned char* s_mode) {
    int buf = l & 1, nxt = buf ^ 1;
    for (int j = threadIdx.x; j < 512; j += TAIL_THREADS) {
        g_sumA[nxt][j] = 0; g_sum2A[nxt][j] = 0ull;
    }
    for (int j = threadIdx.x; j < N; j += TAIL_THREADS) {
        double mean = (double)g_sumA[buf][j] / 16384.0;
        double var  = (double)(long long)g_sum2A[buf][j] / 16384.0 - mean * mean;
        double invstd = 1.0 / sqrt(var + 1e-5);
        double scale = invstd * (double)gam[j];
        double shift = (double)bet[j];
        int thr, mode;
        if (scale > 0.0) {
            double t = fmin(fmax(mean - shift / scale, -1.0e9), 1.0e9);
            thr = (int)ceil(t);  mode = 0;
        } else if (scale < 0.0) {
            double t = fmin(fmax(mean - shift / scale, -1.0e9), 1.0e9);
            thr = (int)floor(t); mode = 1;
        } else {
            mode = 0;
            thr = (shift < 0.0) ? 2147483647 : (-2147483647 - 1);
        }
        s_thr[j] = thr;
        s_mode[j] = (unsigned char)mode;
    }
    __syncthreads();
}

// pack next-layer sign bits: one row per warp iteration, loads batched 8-wide.
template <int C, int NP, int KW>
__device__ void pack_act_layer(const short* __restrict__ a, unsigned* __restrict__ dst,
                               const int* s_thr, const unsigned char* s_mode) {
    const int wid = threadIdx.x >> 5, lane = threadIdx.x & 31;
    const int gw = blockIdx.x * (TAIL_THREADS / 32) + wid;
    const int total = TAIL_CTAS * (TAIL_THREADS / 32);
    for (int row = gw; row < MB; row += total) {
        const short* ar = a + (size_t)row * NP;
        unsigned* dr = dst + (size_t)row * KW;
#pragma unroll
        for (int w0 = 0; w0 < KW; w0 += 8) {
            const int nb = (KW - w0 < 8) ? (KW - w0) : 8;
            int v[8];
#pragma unroll
            for (int k = 0; k < 8; k++) {
                if (k < nb) {
                    int col = (w0 + k) * 32 + lane;
                    v[k] = (col < C) ? (int)ar[col] : 0;
                }
            }
            unsigned m[8];
#pragma unroll
            for (int k = 0; k < 8; k++) {
                if (k < nb) {
                    int col = (w0 + k) * 32 + lane;
                    bool neg = false;
                    if (col < C) {
                        int thr = s_thr[col];
                        neg = s_mode[col] ? (v[k] > thr) : (v[k] < thr);
                    }
                    m[k] = __ballot_sync(0xffffffffu, neg);
                }
            }
            if (lane == 0) {
#pragma unroll
                for (int k = 0; k < 8; k++)
                    if (k < nb) dr[w0 + k] = m[k];
            }
        }
    }
}

// tail GEMM: 64x64 tiles, software-pipelined across tiles.
// Per tile: STS(cur regs) -> sync -> LDG-prefetch(next tile -> regs) ->
// mainloop -> epilogue -> sync. Next tile's global-load latency overlaps
// the current tile's compute. As transposed [w][row] stride 68.
template <int N, int NP, int K, int KW, bool FINAL, int SB>
__device__ void gemm_layer(const unsigned* __restrict__ abits, const unsigned* __restrict__ bbits,
                           const int* __restrict__ sb, short* __restrict__ aout,
                           float* __restrict__ fout, unsigned one, unsigned hi,
                           unsigned* As /*16*68*/, unsigned* Bs /*16*64*/,
                           int* s_sum, unsigned* s_sq) {
    const int tx = threadIdx.x & 15;
    const int ty = threadIdx.x >> 4;
    const int lane = threadIdx.x & 31;
    const int ct = (N + 63) / 64;
    const int ntiles = (MB / 64) * ct;
    const int tid = threadIdx.x;

    if (!FINAL) {
        for (int idx = tid; idx < 512; idx += 256) { s_sum[idx] = 0; s_sq[idx] = 0u; }
    }
    __syncthreads();

    unsigned a_pf[4], b_pf[4];

    int t = blockIdx.x;
    if (t < ntiles) {
        const int row0 = (t / ct) * 64;
        const int col0 = (t % ct) * 64;
#pragma unroll
        for (int i = 0; i < 4; i++) {
            int idx = tid + i * 256;
            int r = idx >> 4, w = idx & 15;
            a_pf[i] = (w < KW) ? abits[(size_t)(row0 + r) * KW + w] : 0u;
        }
#pragma unroll
        for (int i = 0; i < 4; i++) {
            int idx = tid + i * 256;
            int c = idx & 63, w = idx >> 6;
            int col = col0 + c;
            b_pf[i] = (col < N && w < KW) ? bbits[(size_t)col * KW + w] : 0u;
        }
    }

#pragma unroll 1
    while (t < ntiles) {
        // commit prefetched tile to smem
#pragma unroll
        for (int i = 0; i < 4; i++) {
            int idx = tid + i * 256;
            int r = idx >> 4, w = idx & 15;
            As[w * 68 + r] = a_pf[i];
        }
#pragma unroll
        for (int i = 0; i < 4; i++) {
            int idx = tid + i * 256;
            int c = idx & 63, w = idx >> 6;
            Bs[w * 64 + c] = b_pf[i];
        }
        __syncthreads();

        const int row0 = (t / ct) * 64;
        const int col0 = (t % ct) * 64;
        const int tn = t + TAIL_CTAS;
        if (tn < ntiles) {   // prefetch next tile while computing this one
            const int nrow0 = (tn / ct) * 64;
            const int ncol0 = (tn % ct) * 64;
#pragma unroll
            for (int i = 0; i < 4; i++) {
                int idx = tid + i * 256;
                int r = idx >> 4, w = idx & 15;
                a_pf[i] = (w < KW) ? abits[(size_t)(nrow0 + r) * KW + w] : 0u;
            }
#pragma unroll
            for (int i = 0; i < 4; i++) {
                int idx = tid + i * 256;
                int c = idx & 63, w = idx >> 6;
                int col = ncol0 + c;
                b_pf[i] = (col < N && w < KW) ? bbits[(size_t)col * KW + w] : 0u;
            }
        }

        unsigned acc[4][2];
#pragma unroll
        for (int i = 0; i < 4; i++) { acc[i][0] = 0u; acc[i][1] = 0u; }

#pragma unroll
        for (int w = 0; w < KW; w++) {
            uint4 av = *(const uint4*)&As[w * 68 + ty * 4];
            uint4 bv = *(const uint4*)&Bs[w * 64 + tx * 4];
            unsigned a[4] = {av.x, av.y, av.z, av.w};
#pragma unroll
            for (int i = 0; i < 4; i++) {
                acc[i][0] += __popc(a[i] ^ bv.x) * one + __popc(a[i] ^ bv.y) * hi;
                acc[i][1] += __popc(a[i] ^ bv.z) * one + __popc(a[i] ^ bv.w) * hi;
            }
        }

        int sbr[4];
        const int c0b = col0 + tx * 4;
#pragma unroll
        for (int j = 0; j < 4; j++) sbr[j] = sb[c0b + j];

        int s_loc[4];
        unsigned q_loc[4];
#pragma unroll
        for (int j = 0; j < 4; j++) { s_loc[j] = 0; q_loc[j] = 0; }

#pragma unroll
        for (int i = 0; i < 4; i++) {
            int row = row0 + ty * 4 + i;
            int v[4];
#pragma unroll
            for (int jj = 0; jj < 2; jj++) {
                v[jj * 2 + 0] = K - 2 * (int)(acc[i][jj] & 0xFFFFu) + sbr[jj * 2 + 0];
                v[jj * 2 + 1] = K - 2 * (int)(acc[i][jj] >> 16)     + sbr[jj * 2 + 1];
            }
            if (FINAL) {
#pragma unroll
                for (int j = 0; j < 4; j++)
                    if (c0b + j < N) fout[(size_t)row * N + c0b + j] = (float)v[j];
            } else {
                if (c0b + 3 < NP) {
                    *(short4*)(aout + (size_t)row * NP + c0b) =
                        make_short4((short)v[0], (short)v[1], (short)v[2], (short)v[3]);
                } else {
#pragma unroll
                    for (int j = 0; j < 4; j++)
                        if (c0b + j < NP) aout[(size_t)row * NP + c0b + j] = (short)v[j];
                }
#pragma unroll
                for (int j = 0; j < 4; j++) {
                    s_loc[j] += v[j];
                    q_loc[j] += (unsigned)(v[j] * v[j]);
                }
            }
        }
        if (!FINAL) {
#pragma unroll
            for (int j = 0; j < 4; j++) {
                s_loc[j] += __shfl_down_sync(0xffffffffu, s_loc[j], 16);
                q_loc[j] += __shfl_down_sync(0xffffffffu, q_loc[j], 16);
            }
            if (lane < 16) {
                const int cc = col0 + lane * 4;
#pragma unroll
                for (int j = 0; j < 4; j++) {
                    atomicAdd(&s_sum[cc + j], s_loc[j]);
                    atomicAdd(&s_sq[cc + j], q_loc[j]);
                }
            }
        }
        __syncthreads();   // all reads of As/Bs done before next STS
        t = tn;
    }

    if (!FINAL) {
        for (int idx = tid; idx < 512; idx += 256) {
            atomicAdd(&g_sumA[SB][idx], s_sum[idx]);
            atomicAdd(&g_sum2A[SB][idx], (unsigned long long)s_sq[idx]);
        }
    }
}

__global__ void __launch_bounds__(TAIL_THREADS, 3)
tail_kernel(TailPtrs tp, float* __restrict__ fout, unsigned one, unsigned hi) {
    __shared__ unsigned As[16 * 68];
    __shared__ unsigned Bs[16 * 64];
    __shared__ int s_sum[512];
    __shared__ unsigned s_sq[512];
    __shared__ int s_thr[512];
    __shared__ unsigned char s_mode[512];

    thresh_smem(0, tp.gam[0], tp.bet[0], 500, s_thr, s_mode);
    pack_act_layer<500, 500, 16>(g_aout, g_act1, s_thr, s_mode);
    gsync();

    gemm_layer<400, 400, 500, 16, false, 1>(g_act1, g_wb[1], g_sb[1], g_aout, nullptr,
                                            one, hi, As, Bs, s_sum, s_sq);
    gsync();
    thresh_smem(1, tp.gam[1], tp.bet[1], 400, s_thr, s_mode);
    pack_act_layer<400, 400, 13>(g_aout, g_act0, s_thr, s_mode);
    gsync();

    gemm_layer<350, 352, 400, 13, false, 0>(g_act0, g_wb[2], g_sb[2], g_aout, nullptr,
                                            one, hi, As, Bs, s_sum, s_sq);
    gsync();
    thresh_smem(2, tp.gam[2], tp.bet[2], 350, s_thr, s_mode);
    pack_act_layer<350, 352, 11>(g_aout, g_act1, s_thr, s_mode);
    gsync();

    gemm_layer<300, 300, 350, 11, false, 1>(g_act1, g_wb[3], g_sb[3], g_aout, nullptr,
                                            one, hi, As, Bs, s_sum, s_sq);
    gsync();
    thresh_smem(3, tp.gam[3], tp.bet[3], 300, s_thr, s_mode);
    pack_act_layer<300, 300, 10>(g_aout, g_act0, s_thr, s_mode);
    gsync();

    gemm_layer<300, 300, 300, 10, false, 0>(g_act0, g_wb[4], g_sb[4], g_aout, nullptr,
                                            one, hi, As, Bs, s_sum, s_sq);
    gsync();
    thresh_smem(4, tp.gam[4], tp.bet[4], 300, s_thr, s_mode);
    pack_act_layer<300, 300, 10>(g_aout, g_act1, s_thr, s_mode);
    gsync();

    gemm_layer<35, 35, 300, 10, true, 0>(g_act1, g_wb[5], g_sb[5], nullptr, fout,
                                         one, hi, As, Bs, s_sum, s_sq);
}

// ---------------- host orchestration ----------------
extern "C" void kernel_launch(void* const* d_in, const int* in_sizes, int n_in,
                              void* d_out, int out_size) {
    (void)in_sizes; (void)n_in; (void)out_size;
    static const int LK[6]  = {4096, 500, 400, 350, 300, 300};
    static const int LN[6]  = {500, 400, 350, 300, 300, 35};
    static const int LKW[6] = {128, 16, 13, 11, 10, 10};

    const float* x = (const float*)d_in[0];
    const float* W[6]; const float* bb[6];
    TailPtrs tp;
    for (int l = 0; l < 5; l++) {
        W[l]      = (const float*)d_in[1 + 4 * l];
        bb[l]     = (const float*)d_in[2 + 4 * l];
        tp.gam[l] = (const float*)d_in[3 + 4 * l];
        tp.bet[l] = (const float*)d_in[4 + 4 * l];
    }
    W[5]  = (const float*)d_in[21];
    bb[5] = (const float*)d_in[22];

    unsigned *act0, *wb;
    int *sb;
    short *aout;
    cudaGetSymbolAddress((void**)&act0, g_act0);
    cudaGetSymbolAddress((void**)&wb,   g_wb);
    cudaGetSymbolAddress((void**)&sb,   g_sb);
    cudaGetSymbolAddress((void**)&aout, g_aout);

    BiasPtrs bp;
    for (int l = 0; l < 6; l++) bp.b[l] = bb[l];

    PackRegions pr;
    pr.src[0] = x; pr.dst[0] = act0;
    pr.R[0] = MB; pr.C[0] = 4096; pr.KW[0] = 128; pr.G[0] = 32;
    for (int l = 0; l < 6; l++) {
        pr.src[1 + l] = W[l];
        pr.dst[1 + l] = wb + (size_t)l * 64000;
        pr.R[1 + l] = LN[l]; pr.C[1 + l] = LK[l]; pr.KW[1 + l] = LKW[l];
        pr.G[1 + l] = (LKW[l] + 3) / 4;
    }
    pr.total = 0;
    for (int r = 0; r < 7; r++) {
        pr.units[r] = (long long)pr.R[r] * pr.G[r];
        pr.total += pr.units[r];
    }

    // 1: prep
    prep_kernel<<<1, 512>>>(bp);
    // 2: all sign packing
    pack_all_kernel<<<2048, 256>>>(pr);
    // 3: gemm1 + fused stats
    {
        dim3 grid(8, MB / 128);
        gemm1_kernel<<<grid, 256>>>(act0, wb, sb, aout, 1u, 65536u);
    }
    // 4: fused persistent tail (ncu capture slot)
    tail_kernel<<<TAIL_CTAS, TAIL_THREADS>>>(tp, (float*)d_out, 1u, 65536u);
}